// round 6
// baseline (speedup 1.0000x reference)
#include <cuda_runtime.h>
#include <cstdint>

#define N_NODES_MAX 50000
#define D_FEAT 128
#define H1 128
#define H2 64

// Scratch: per-node precomputed attention contributions (bias folded into A1).
__device__ float g_A1[N_NODES_MAX * H2];
__device__ float g_A2[N_NODES_MAX * H2];
__device__ int   g_edges_are_i64;   // 1 if edge buffer is int64, 0 if int32

// ---------------- Edge dtype detection ----------------
// If edges are int64 (values < 50000, nonneg), every odd 32-bit word is the
// zero upper half. Under int32 data (uniform in [0, 50000)), the probability
// that 1024 odd words are all zero is ~0.
extern "C" __global__ void detect_edge_dtype_kernel(const int* __restrict__ edges_w)
{
    __shared__ int any_nonzero;
    if (threadIdx.x == 0) any_nonzero = 0;
    __syncthreads();
    // check odd words 1,3,...,2047
    int w = edges_w[2 * threadIdx.x + 1];          // 1024 threads
    if (w != 0) atomicOr(&any_nonzero, 1);
    __syncthreads();
    if (threadIdx.x == 0) g_edges_are_i64 = (any_nonzero == 0) ? 1 : 0;
}

// ---------------- Node precompute kernel ----------------
// gridDim.x = ceil(nNodes/128), gridDim.y = 2 (path 0 = nb/A1, path 1 = self/A2)
// 256 threads. Per block: 128 nodes.
// Phase 1: H[128][128] = relu(F @ W + b)       (8x8 micro-tile per thread)
// Phase 2: A[128][64]  = H @ Wa (+ b_att1 for path 0)  (8x4 micro-tile)
#define TM 128
#define SF 132           // padded row stride for F/H tile (floats)
#define SW 132           // padded row stride for W tile
#define SA 68            // padded row stride for Wa tile
#define SMEM_FH_BYTES (TM * SF * 4)
#define SMEM_W_BYTES  (D_FEAT * SW * 4)
#define SMEM_WA_BYTES (H1 * SA * 4)
#define NODE_SMEM_BYTES (SMEM_FH_BYTES + SMEM_W_BYTES + SMEM_WA_BYTES)

extern "C" __global__ void __launch_bounds__(256, 1)
node_precompute_kernel(const float* __restrict__ features,
                       const float* __restrict__ W_nb,
                       const float* __restrict__ b_nb,
                       const float* __restrict__ W_self,
                       const float* __restrict__ b_self,
                       const float* __restrict__ W_att1,
                       const float* __restrict__ b_att1,
                       int nNodes)
{
    extern __shared__ float smem[];
    float* FH = smem;                                  // [TM][SF] (F, later H)
    float* Ws = smem + TM * SF;                        // [D_FEAT][SW]
    float* Wa = smem + TM * SF + D_FEAT * SW;          // [H1][SA]

    const int tid  = threadIdx.x;
    const int path = blockIdx.y;                       // 0: nb -> A1, 1: self -> A2
    const int node0 = blockIdx.x * TM;
    const int valid = min(TM, nNodes - node0);

    const float* W  = (path == 0) ? W_nb : W_self;
    const float* bW = (path == 0) ? b_nb : b_self;
    const float* WaG = W_att1 + (size_t)path * H1 * H2;   // rows [path*128 .. +128) of [256][64]
    float* Aout = (path == 0) ? g_A1 : g_A2;

    // ---- Load F tile (zero-pad invalid rows) ----
    #pragma unroll
    for (int idx = tid; idx < TM * (D_FEAT / 4); idx += 256) {
        int row = idx >> 5;            // /32 float4s per row
        int c4  = idx & 31;
        float4 v = make_float4(0.f, 0.f, 0.f, 0.f);
        if (row < valid)
            v = *reinterpret_cast<const float4*>(&features[(size_t)(node0 + row) * D_FEAT + c4 * 4]);
        *reinterpret_cast<float4*>(&FH[row * SF + c4 * 4]) = v;
    }
    // ---- Load W tile ----
    #pragma unroll
    for (int idx = tid; idx < D_FEAT * (H1 / 4); idx += 256) {
        int row = idx >> 5;
        int c4  = idx & 31;
        float4 v = *reinterpret_cast<const float4*>(&W[(size_t)row * H1 + c4 * 4]);
        *reinterpret_cast<float4*>(&Ws[row * SW + c4 * 4]) = v;
    }
    // ---- Load Wa tile ----
    #pragma unroll
    for (int idx = tid; idx < H1 * (H2 / 4); idx += 256) {
        int row = idx >> 4;            // /16 float4s per row
        int c4  = idx & 15;
        float4 v = *reinterpret_cast<const float4*>(&WaG[(size_t)row * H2 + c4 * 4]);
        *reinterpret_cast<float4*>(&Wa[row * SA + c4 * 4]) = v;
    }
    __syncthreads();

    // ---- Phase 1: H = relu(F @ W + b) ----
    const int ty = tid >> 4;           // 0..15  -> 8 rows each
    const int tx = tid & 15;           // 0..15  -> cols tx*4..+3 and 64+tx*4..+3
    float c1[8][8];
    #pragma unroll
    for (int i = 0; i < 8; i++)
        #pragma unroll
        for (int j = 0; j < 8; j++) c1[i][j] = 0.f;

    #pragma unroll 4
    for (int k = 0; k < D_FEAT; k++) {
        float a[8];
        #pragma unroll
        for (int i = 0; i < 8; i++) a[i] = FH[(ty * 8 + i) * SF + k];
        float b[8];
        #pragma unroll
        for (int j = 0; j < 4; j++) {
            b[j]     = Ws[k * SW + tx * 4 + j];
            b[4 + j] = Ws[k * SW + 64 + tx * 4 + j];
        }
        #pragma unroll
        for (int i = 0; i < 8; i++)
            #pragma unroll
            for (int j = 0; j < 8; j++)
                c1[i][j] = fmaf(a[i], b[j], c1[i][j]);
    }

    // bias + relu
    float bb[8];
    #pragma unroll
    for (int j = 0; j < 4; j++) {
        bb[j]     = __ldg(&bW[tx * 4 + j]);
        bb[4 + j] = __ldg(&bW[64 + tx * 4 + j]);
    }
    __syncthreads();   // all reads of F done -> safe to overwrite FH with H

    #pragma unroll
    for (int i = 0; i < 8; i++) {
        float4 v0, v1;
        v0.x = fmaxf(c1[i][0] + bb[0], 0.f);
        v0.y = fmaxf(c1[i][1] + bb[1], 0.f);
        v0.z = fmaxf(c1[i][2] + bb[2], 0.f);
        v0.w = fmaxf(c1[i][3] + bb[3], 0.f);
        v1.x = fmaxf(c1[i][4] + bb[4], 0.f);
        v1.y = fmaxf(c1[i][5] + bb[5], 0.f);
        v1.z = fmaxf(c1[i][6] + bb[6], 0.f);
        v1.w = fmaxf(c1[i][7] + bb[7], 0.f);
        int m = ty * 8 + i;
        *reinterpret_cast<float4*>(&FH[m * SF + tx * 4])      = v0;
        *reinterpret_cast<float4*>(&FH[m * SF + 64 + tx * 4]) = v1;
    }
    __syncthreads();

    // ---- Phase 2: A = H @ Wa (+ b_att1 for path 0) ----
    float c2[8][4];
    #pragma unroll
    for (int i = 0; i < 8; i++)
        #pragma unroll
        for (int j = 0; j < 4; j++) c2[i][j] = 0.f;

    #pragma unroll 4
    for (int k = 0; k < H1; k++) {
        float a[8];
        #pragma unroll
        for (int i = 0; i < 8; i++) a[i] = FH[(ty * 8 + i) * SF + k];
        float b[4];
        #pragma unroll
        for (int j = 0; j < 4; j++) b[j] = Wa[k * SA + tx * 4 + j];
        #pragma unroll
        for (int i = 0; i < 8; i++)
            #pragma unroll
            for (int j = 0; j < 4; j++)
                c2[i][j] = fmaf(a[i], b[j], c2[i][j]);
    }

    float ba[4] = {0.f, 0.f, 0.f, 0.f};
    if (path == 0) {
        #pragma unroll
        for (int j = 0; j < 4; j++) ba[j] = __ldg(&b_att1[tx * 4 + j]);
    }

    #pragma unroll
    for (int i = 0; i < 8; i++) {
        int m = ty * 8 + i;
        if (m < valid) {
            float4 v;
            v.x = c2[i][0] + ba[0];
            v.y = c2[i][1] + ba[1];
            v.z = c2[i][2] + ba[2];
            v.w = c2[i][3] + ba[3];
            *reinterpret_cast<float4*>(&Aout[(size_t)(node0 + m) * H2 + tx * 4]) = v;
        }
    }
}

// ---------------- Edge kernel ----------------
// One warp per edge: out[e] = relu(A1[n1] + A2[n2]) . W_att2 + b_att2
extern "C" __global__ void __launch_bounds__(256)
edge_kernel(const void* __restrict__ edges_raw,
            const float* __restrict__ W_att2,
            const float* __restrict__ b_att2,
            float* __restrict__ out,
            int nEdges)
{
    const int warp = (blockIdx.x * blockDim.x + threadIdx.x) >> 5;
    const int lane = threadIdx.x & 31;
    if (warp >= nEdges) return;

    int n1, n2;
    if (g_edges_are_i64) {
        const longlong2 e =
            *reinterpret_cast<const longlong2*>((const char*)edges_raw + 16 * (size_t)warp);
        n1 = (int)e.x;
        n2 = (int)e.y;
    } else {
        const int2 e =
            *reinterpret_cast<const int2*>((const char*)edges_raw + 8 * (size_t)warp);
        n1 = e.x;
        n2 = e.y;
    }

    const float2 a = *reinterpret_cast<const float2*>(&g_A1[(size_t)n1 * H2 + lane * 2]);
    const float2 b = *reinterpret_cast<const float2*>(&g_A2[(size_t)n2 * H2 + lane * 2]);
    const float2 w = *reinterpret_cast<const float2*>(&W_att2[lane * 2]);

    float x = fmaxf(a.x + b.x, 0.f);
    float y = fmaxf(a.y + b.y, 0.f);
    float s = fmaf(x, w.x, y * w.y);

    #pragma unroll
    for (int off = 16; off > 0; off >>= 1)
        s += __shfl_xor_sync(0xFFFFFFFFu, s, off);

    if (lane == 0) out[warp] = s + __ldg(&b_att2[0]);
}

// ---------------- Launch ----------------
extern "C" void kernel_launch(void* const* d_in, const int* in_sizes, int n_in,
                              void* d_out, int out_size)
{
    const float* features = (const float*)d_in[0];
    const void*  edges    = d_in[1];
    const float* W_nb     = (const float*)d_in[2];
    const float* b_nb     = (const float*)d_in[3];
    const float* W_self   = (const float*)d_in[4];
    const float* b_self   = (const float*)d_in[5];
    const float* W_att1   = (const float*)d_in[6];
    const float* b_att1   = (const float*)d_in[7];
    const float* W_att2   = (const float*)d_in[8];
    const float* b_att2   = (const float*)d_in[9];
    float* out = (float*)d_out;

    const int nNodes = in_sizes[0] / D_FEAT;
    const int nEdges = in_sizes[1] / 2;

    detect_edge_dtype_kernel<<<1, 1024>>>((const int*)edges);

    cudaFuncSetAttribute(node_precompute_kernel,
                         cudaFuncAttributeMaxDynamicSharedMemorySize, NODE_SMEM_BYTES);

    dim3 gridN((nNodes + TM - 1) / TM, 2);
    node_precompute_kernel<<<gridN, 256, NODE_SMEM_BYTES>>>(
        features, W_nb, b_nb, W_self, b_self, W_att1, b_att1, nNodes);

    const int warpsPerBlock = 256 / 32;
    int gridE = (nEdges + warpsPerBlock - 1) / warpsPerBlock;
    edge_kernel<<<gridE, 256>>>(edges, W_att2, b_att2, out, nEdges);
}

// round 8
// speedup vs baseline: 1.9523x; 1.9523x over previous
#include <cuda_runtime.h>
#include <cstdint>

#define N_NODES_MAX 50000
#define D_FEAT 128
#define H1 128
#define H2 64

// Scratch: per-node precomputed attention contributions (bias folded into A1).
__device__ float g_A1[N_NODES_MAX * H2];
__device__ float g_A2[N_NODES_MAX * H2];
__device__ int   g_edges_are_i64;   // 1 if edge buffer is int64, 0 if int32

// ---------------- smem layout ----------------
#define TM 128
#define SF 132           // padded row stride for F/H tile (floats)
#define SW 132           // padded row stride for W tile
#define SA 68            // padded row stride for Wa tile
#define NODE_SMEM_BYTES ((TM * SF + D_FEAT * SW + H1 * SA) * 4)

// 3xTF32 helpers -------------------------------------------------------------
// Tensor core reads only the top 19 bits (s|8e|10m) of a .b32 tf32 operand.
// hi = exact truncation (mask), lo = exact fp32 remainder (Sterbenz: exact).
// hi*hi + hi*lo + lo*hi recovers ~fp32 precision (missing lo*lo ~ 2^-22).
__device__ __forceinline__ void split_tf32(float x, uint32_t& hi, uint32_t& lo) {
    uint32_t xb = __float_as_uint(x);
    hi = xb & 0xFFFFE000u;
    lo = __float_as_uint(x - __uint_as_float(hi));
}

__device__ __forceinline__ void mma_tf32(float* d, const uint32_t* a, const uint32_t* b) {
    asm volatile(
        "mma.sync.aligned.m16n8k8.row.col.f32.tf32.tf32.f32 "
        "{%0,%1,%2,%3}, {%4,%5,%6,%7}, {%8,%9}, {%0,%1,%2,%3};\n"
        : "+f"(d[0]), "+f"(d[1]), "+f"(d[2]), "+f"(d[3])
        : "r"(a[0]), "r"(a[1]), "r"(a[2]), "r"(a[3]), "r"(b[0]), "r"(b[1]));
}

// ---------------- Node precompute kernel (tensor-core) ----------------
// gridDim.x = ceil(nNodes/128), gridDim.y = 2 (path 0 = nb/A1, path 1 = self/A2)
// 256 threads = 8 warps, warp grid 2(m) x 4(n).
// Phase 1: H[128][128] = relu(F @ W + b)       warp tile 64x32  (mf=4, nf=4)
// Phase 2: A[128][64]  = H @ Wa (+ b_att1)     warp tile 64x16  (mf=4, nf=2)
// Block (0,0) additionally detects edge dtype (int64 vs int32).
extern "C" __global__ void __launch_bounds__(256, 1)
node_precompute_kernel(const float* __restrict__ features,
                       const int*   __restrict__ edges_words,
                       const float* __restrict__ W_nb,
                       const float* __restrict__ b_nb,
                       const float* __restrict__ W_self,
                       const float* __restrict__ b_self,
                       const float* __restrict__ W_att1,
                       const float* __restrict__ b_att1,
                       int nNodes)
{
    extern __shared__ float smem[];
    float* FH = smem;                                  // [TM][SF] (F, later H)
    float* Ws = smem + TM * SF;                        // [D_FEAT][SW]
    float* Wa = smem + TM * SF + D_FEAT * SW;          // [H1][SA]

    const int tid  = threadIdx.x;
    const int path = blockIdx.y;
    const int node0 = blockIdx.x * TM;
    const int valid = min(TM, nNodes - node0);

    // ---- Edge dtype detection (block (0,0) only; block-uniform branch) ----
    // int64 edges (values < 50000, nonneg) => every odd 32-bit word is zero.
    if (blockIdx.x == 0 && path == 0) {
        int nz = 0;
        for (int i = tid; i < 2048; i += 256) nz |= edges_words[2 * i + 1];
        int any = __syncthreads_or(nz);
        if (tid == 0) g_edges_are_i64 = (any == 0) ? 1 : 0;
    }

    const float* W   = (path == 0) ? W_nb : W_self;
    const float* bW  = (path == 0) ? b_nb : b_self;
    const float* WaG = W_att1 + (size_t)path * H1 * H2;   // rows [path*128, +128) of [256][64]
    float* Aout = (path == 0) ? g_A1 : g_A2;

    // ---- Stage F tile (zero-pad invalid rows) ----
    #pragma unroll
    for (int idx = tid; idx < TM * (D_FEAT / 4); idx += 256) {
        int row = idx >> 5;
        int c4  = idx & 31;
        float4 v = make_float4(0.f, 0.f, 0.f, 0.f);
        if (row < valid)
            v = *reinterpret_cast<const float4*>(&features[(size_t)(node0 + row) * D_FEAT + c4 * 4]);
        *reinterpret_cast<float4*>(&FH[row * SF + c4 * 4]) = v;
    }
    // ---- Stage W ----
    #pragma unroll
    for (int idx = tid; idx < D_FEAT * (H1 / 4); idx += 256) {
        int row = idx >> 5;
        int c4  = idx & 31;
        float4 v = *reinterpret_cast<const float4*>(&W[(size_t)row * H1 + c4 * 4]);
        *reinterpret_cast<float4*>(&Ws[row * SW + c4 * 4]) = v;
    }
    // ---- Stage Wa ----
    #pragma unroll
    for (int idx = tid; idx < H1 * (H2 / 4); idx += 256) {
        int row = idx >> 4;
        int c4  = idx & 15;
        float4 v = *reinterpret_cast<const float4*>(&WaG[(size_t)row * H2 + c4 * 4]);
        *reinterpret_cast<float4*>(&Wa[row * SA + c4 * 4]) = v;
    }
    __syncthreads();

    const int lane = tid & 31;
    const int wid  = tid >> 5;
    const int gid  = lane >> 2;        // group id 0..7
    const int tig  = lane & 3;         // thread-in-group 0..3
    const int wm   = wid >> 2;         // 0..1
    const int wn   = wid & 3;          // 0..3

    // ================= Phase 1: H = relu(F @ W + b) =================
    float acc[4][4][4];
    #pragma unroll
    for (int mf = 0; mf < 4; mf++)
        #pragma unroll
        for (int nf = 0; nf < 4; nf++)
            #pragma unroll
            for (int r = 0; r < 4; r++) acc[mf][nf][r] = 0.f;

    for (int kb = 0; kb < D_FEAT / 8; kb++) {
        const int k0 = kb * 8;
        uint32_t ahi[4][4], alo[4][4];
        #pragma unroll
        for (int mf = 0; mf < 4; mf++) {
            const float* fp = &FH[(wm * 64 + mf * 16 + gid) * SF + k0 + tig];
            split_tf32(fp[0],          ahi[mf][0], alo[mf][0]);
            split_tf32(fp[8 * SF],     ahi[mf][1], alo[mf][1]);
            split_tf32(fp[4],          ahi[mf][2], alo[mf][2]);
            split_tf32(fp[8 * SF + 4], ahi[mf][3], alo[mf][3]);
        }
        uint32_t bhi[4][2], blo[4][2];
        #pragma unroll
        for (int nf = 0; nf < 4; nf++) {
            const float* wp = &Ws[(k0 + tig) * SW + wn * 32 + nf * 8 + gid];
            split_tf32(wp[0],      bhi[nf][0], blo[nf][0]);
            split_tf32(wp[4 * SW], bhi[nf][1], blo[nf][1]);
        }
        #pragma unroll
        for (int mf = 0; mf < 4; mf++)
            #pragma unroll
            for (int nf = 0; nf < 4; nf++) {
                mma_tf32(acc[mf][nf], ahi[mf], bhi[nf]);
                mma_tf32(acc[mf][nf], ahi[mf], blo[nf]);
                mma_tf32(acc[mf][nf], alo[mf], bhi[nf]);
            }
    }

    // bias + relu, write H back into FH (all F reads complete after barrier)
    float bias0[4], bias1[4];
    #pragma unroll
    for (int nf = 0; nf < 4; nf++) {
        int c = wn * 32 + nf * 8 + 2 * tig;
        bias0[nf] = __ldg(&bW[c]);
        bias1[nf] = __ldg(&bW[c + 1]);
    }
    __syncthreads();

    #pragma unroll
    for (int mf = 0; mf < 4; mf++) {
        int r0 = wm * 64 + mf * 16 + gid;
        #pragma unroll
        for (int nf = 0; nf < 4; nf++) {
            int c = wn * 32 + nf * 8 + 2 * tig;
            float2 v0, v1;
            v0.x = fmaxf(acc[mf][nf][0] + bias0[nf], 0.f);
            v0.y = fmaxf(acc[mf][nf][1] + bias1[nf], 0.f);
            v1.x = fmaxf(acc[mf][nf][2] + bias0[nf], 0.f);
            v1.y = fmaxf(acc[mf][nf][3] + bias1[nf], 0.f);
            *reinterpret_cast<float2*>(&FH[r0 * SF + c])       = v0;
            *reinterpret_cast<float2*>(&FH[(r0 + 8) * SF + c]) = v1;
        }
    }
    __syncthreads();

    // ================= Phase 2: A = H @ Wa (+ b_att1 path 0) =================
    float acc2[4][2][4];
    #pragma unroll
    for (int mf = 0; mf < 4; mf++)
        #pragma unroll
        for (int nf = 0; nf < 2; nf++)
            #pragma unroll
            for (int r = 0; r < 4; r++) acc2[mf][nf][r] = 0.f;

    for (int kb = 0; kb < H1 / 8; kb++) {
        const int k0 = kb * 8;
        uint32_t ahi[4][4], alo[4][4];
        #pragma unroll
        for (int mf = 0; mf < 4; mf++) {
            const float* fp = &FH[(wm * 64 + mf * 16 + gid) * SF + k0 + tig];
            split_tf32(fp[0],          ahi[mf][0], alo[mf][0]);
            split_tf32(fp[8 * SF],     ahi[mf][1], alo[mf][1]);
            split_tf32(fp[4],          ahi[mf][2], alo[mf][2]);
            split_tf32(fp[8 * SF + 4], ahi[mf][3], alo[mf][3]);
        }
        uint32_t bhi[2][2], blo[2][2];
        #pragma unroll
        for (int nf = 0; nf < 2; nf++) {
            const float* wp = &Wa[(k0 + tig) * SA + wn * 16 + nf * 8 + gid];
            split_tf32(wp[0],      bhi[nf][0], blo[nf][0]);
            split_tf32(wp[4 * SA], bhi[nf][1], blo[nf][1]);
        }
        #pragma unroll
        for (int mf = 0; mf < 4; mf++)
            #pragma unroll
            for (int nf = 0; nf < 2; nf++) {
                mma_tf32(acc2[mf][nf], ahi[mf], bhi[nf]);
                mma_tf32(acc2[mf][nf], ahi[mf], blo[nf]);
                mma_tf32(acc2[mf][nf], alo[mf], bhi[nf]);
            }
    }

    float ba0[2] = {0.f, 0.f}, ba1[2] = {0.f, 0.f};
    if (path == 0) {
        #pragma unroll
        for (int nf = 0; nf < 2; nf++) {
            int c = wn * 16 + nf * 8 + 2 * tig;
            ba0[nf] = __ldg(&b_att1[c]);
            ba1[nf] = __ldg(&b_att1[c + 1]);
        }
    }

    #pragma unroll
    for (int mf = 0; mf < 4; mf++) {
        int r0 = wm * 64 + mf * 16 + gid;
        #pragma unroll
        for (int nf = 0; nf < 2; nf++) {
            int c = wn * 16 + nf * 8 + 2 * tig;
            if (r0 < valid) {
                float2 v;
                v.x = acc2[mf][nf][0] + ba0[nf];
                v.y = acc2[mf][nf][1] + ba1[nf];
                *reinterpret_cast<float2*>(&Aout[(size_t)(node0 + r0) * H2 + c]) = v;
            }
            if (r0 + 8 < valid) {
                float2 v;
                v.x = acc2[mf][nf][2] + ba0[nf];
                v.y = acc2[mf][nf][3] + ba1[nf];
                *reinterpret_cast<float2*>(&Aout[(size_t)(node0 + r0 + 8) * H2 + c]) = v;
            }
        }
    }
}

// ---------------- Edge kernel ----------------
// One warp per edge: out[e] = relu(A1[n1] + A2[n2]) . W_att2 + b_att2
extern "C" __global__ void __launch_bounds__(256)
edge_kernel(const void* __restrict__ edges_raw,
            const float* __restrict__ W_att2,
            const float* __restrict__ b_att2,
            float* __restrict__ out,
            int nEdges)
{
    const int warp = (blockIdx.x * blockDim.x + threadIdx.x) >> 5;
    const int lane = threadIdx.x & 31;
    if (warp >= nEdges) return;

    int n1, n2;
    if (g_edges_are_i64) {
        const longlong2 e =
            *reinterpret_cast<const longlong2*>((const char*)edges_raw + 16 * (size_t)warp);
        n1 = (int)e.x;
        n2 = (int)e.y;
    } else {
        const int2 e =
            *reinterpret_cast<const int2*>((const char*)edges_raw + 8 * (size_t)warp);
        n1 = e.x;
        n2 = e.y;
    }

    const float2 a = *reinterpret_cast<const float2*>(&g_A1[(size_t)n1 * H2 + lane * 2]);
    const float2 b = *reinterpret_cast<const float2*>(&g_A2[(size_t)n2 * H2 + lane * 2]);
    const float2 w = *reinterpret_cast<const float2*>(&W_att2[lane * 2]);

    float x = fmaxf(a.x + b.x, 0.f);
    float y = fmaxf(a.y + b.y, 0.f);
    float s = fmaf(x, w.x, y * w.y);

    #pragma unroll
    for (int off = 16; off > 0; off >>= 1)
        s += __shfl_xor_sync(0xFFFFFFFFu, s, off);

    if (lane == 0) out[warp] = s + __ldg(&b_att2[0]);
}

// ---------------- Launch ----------------
extern "C" void kernel_launch(void* const* d_in, const int* in_sizes, int n_in,
                              void* d_out, int out_size)
{
    const float* features = (const float*)d_in[0];
    const void*  edges    = d_in[1];
    const float* W_nb     = (const float*)d_in[2];
    const float* b_nb     = (const float*)d_in[3];
    const float* W_self   = (const float*)d_in[4];
    const float* b_self   = (const float*)d_in[5];
    const float* W_att1   = (const float*)d_in[6];
    const float* b_att1   = (const float*)d_in[7];
    const float* W_att2   = (const float*)d_in[8];
    const float* b_att2   = (const float*)d_in[9];
    float* out = (float*)d_out;

    const int nNodes = in_sizes[0] / D_FEAT;
    const int nEdges = in_sizes[1] / 2;

    cudaFuncSetAttribute(node_precompute_kernel,
                         cudaFuncAttributeMaxDynamicSharedMemorySize, NODE_SMEM_BYTES);

    dim3 gridN((nNodes + TM - 1) / TM, 2);
    node_precompute_kernel<<<gridN, 256, NODE_SMEM_BYTES>>>(
        features, (const int*)edges, W_nb, b_nb, W_self, b_self, W_att1, b_att1, nNodes);

    const int warpsPerBlock = 256 / 32;
    int gridE = (nEdges + warpsPerBlock - 1) / warpsPerBlock;
    edge_kernel<<<gridE, 256>>>(edges, W_att2, b_att2, out, nEdges);
}

// round 9
// speedup vs baseline: 2.3302x; 1.1936x over previous
#include <cuda_runtime.h>
#include <cstdint>

#define N_NODES_MAX 50000
#define D_FEAT 128
#define H1 128
#define H2 64

// Scratch: per-node precomputed attention contributions (bias folded into A1).
__device__ float g_A1[N_NODES_MAX * H2];
__device__ float g_A2[N_NODES_MAX * H2];
__device__ int   g_edges_are_i64;   // 1 if edge buffer is int64, 0 if int32

// ---------------- smem layout ----------------
#define TM 128
#define SF 132           // padded row stride for F/H tile (floats)
#define SW 132           // padded row stride for W tile
#define SA 68            // padded row stride for Wa tile
#define NODE_SMEM_BYTES ((TM * SF + D_FEAT * SW + H1 * SA) * 4)

// 3xTF32 helpers -------------------------------------------------------------
// Tensor core reads only the top 19 bits (s|8e|10m) of a .b32 tf32 operand.
// hi = exact truncation (mask), lo = exact fp32 remainder.
// hi*hi + hi*lo + lo*hi recovers ~fp32 precision (missing lo*lo ~ 2^-22).
__device__ __forceinline__ void split_tf32(float x, uint32_t& hi, uint32_t& lo) {
    uint32_t xb = __float_as_uint(x);
    hi = xb & 0xFFFFE000u;
    lo = __float_as_uint(x - __uint_as_float(hi));
}

__device__ __forceinline__ void mma_tf32(float* d, const uint32_t* a, const uint32_t* b) {
    asm volatile(
        "mma.sync.aligned.m16n8k8.row.col.f32.tf32.tf32.f32 "
        "{%0,%1,%2,%3}, {%4,%5,%6,%7}, {%8,%9}, {%0,%1,%2,%3};\n"
        : "+f"(d[0]), "+f"(d[1]), "+f"(d[2]), "+f"(d[3])
        : "r"(a[0]), "r"(a[1]), "r"(a[2]), "r"(a[3]), "r"(b[0]), "r"(b[1]));
}

// ---------------- Node precompute kernel (tensor-core) ----------------
// gridDim.x = ceil(nNodes/128), gridDim.y = 2 (path 0 = nb/A1, path 1 = self/A2)
// 256 threads = 8 warps, warp grid 2(m) x 4(n).
// Phase 1: H[128][128] = relu(F @ W + b)       warp tile 64x32  (mf=4, nf=4)
// Phase 2: A[128][64]  = H @ Wa (+ b_att1)     warp tile 64x16  (mf=4, nf=2)
// Block (0,0) additionally detects edge dtype (int64 vs int32).
extern "C" __global__ void __launch_bounds__(256, 1)
node_precompute_kernel(const float* __restrict__ features,
                       const int*   __restrict__ edges_words,
                       const float* __restrict__ W_nb,
                       const float* __restrict__ b_nb,
                       const float* __restrict__ W_self,
                       const float* __restrict__ b_self,
                       const float* __restrict__ W_att1,
                       const float* __restrict__ b_att1,
                       int nNodes)
{
    extern __shared__ float smem[];
    float* FH = smem;                                  // [TM][SF] (F, later H)
    float* Ws = smem + TM * SF;                        // [D_FEAT][SW]
    float* Wa = smem + TM * SF + D_FEAT * SW;          // [H1][SA]

    const int tid  = threadIdx.x;
    const int path = blockIdx.y;
    const int node0 = blockIdx.x * TM;
    const int valid = min(TM, nNodes - node0);

    // ---- Edge dtype detection (block (0,0) only; block-uniform branch) ----
    // int64 edges (values < 50000, nonneg) => every odd 32-bit word is zero.
    if (blockIdx.x == 0 && path == 0) {
        int nz = 0;
        for (int i = tid; i < 2048; i += 256) nz |= edges_words[2 * i + 1];
        int any = __syncthreads_or(nz);
        if (tid == 0) g_edges_are_i64 = (any == 0) ? 1 : 0;
    }

    const float* W   = (path == 0) ? W_nb : W_self;
    const float* bW  = (path == 0) ? b_nb : b_self;
    const float* WaG = W_att1 + (size_t)path * H1 * H2;   // rows [path*128, +128) of [256][64]
    float* Aout = (path == 0) ? g_A1 : g_A2;

    // ---- Stage F tile (zero-pad invalid rows) ----
    #pragma unroll
    for (int idx = tid; idx < TM * (D_FEAT / 4); idx += 256) {
        int row = idx >> 5;
        int c4  = idx & 31;
        float4 v = make_float4(0.f, 0.f, 0.f, 0.f);
        if (row < valid)
            v = *reinterpret_cast<const float4*>(&features[(size_t)(node0 + row) * D_FEAT + c4 * 4]);
        *reinterpret_cast<float4*>(&FH[row * SF + c4 * 4]) = v;
    }
    // ---- Stage W ----
    #pragma unroll
    for (int idx = tid; idx < D_FEAT * (H1 / 4); idx += 256) {
        int row = idx >> 5;
        int c4  = idx & 31;
        float4 v = *reinterpret_cast<const float4*>(&W[(size_t)row * H1 + c4 * 4]);
        *reinterpret_cast<float4*>(&Ws[row * SW + c4 * 4]) = v;
    }
    // ---- Stage Wa ----
    #pragma unroll
    for (int idx = tid; idx < H1 * (H2 / 4); idx += 256) {
        int row = idx >> 4;
        int c4  = idx & 15;
        float4 v = *reinterpret_cast<const float4*>(&WaG[(size_t)row * H2 + c4 * 4]);
        *reinterpret_cast<float4*>(&Wa[row * SA + c4 * 4]) = v;
    }
    __syncthreads();

    const int lane = tid & 31;
    const int wid  = tid >> 5;
    const int gid  = lane >> 2;        // group id 0..7
    const int tig  = lane & 3;         // thread-in-group 0..3
    const int wm   = wid >> 2;         // 0..1
    const int wn   = wid & 3;          // 0..3

    // ================= Phase 1: H = relu(F @ W + b) =================
    float acc[4][4][4];
    #pragma unroll
    for (int mf = 0; mf < 4; mf++)
        #pragma unroll
        for (int nf = 0; nf < 4; nf++)
            #pragma unroll
            for (int r = 0; r < 4; r++) acc[mf][nf][r] = 0.f;

    for (int kb = 0; kb < D_FEAT / 8; kb++) {
        const int k0 = kb * 8;
        uint32_t ahi[4][4], alo[4][4];
        #pragma unroll
        for (int mf = 0; mf < 4; mf++) {
            const float* fp = &FH[(wm * 64 + mf * 16 + gid) * SF + k0 + tig];
            split_tf32(fp[0],          ahi[mf][0], alo[mf][0]);
            split_tf32(fp[8 * SF],     ahi[mf][1], alo[mf][1]);
            split_tf32(fp[4],          ahi[mf][2], alo[mf][2]);
            split_tf32(fp[8 * SF + 4], ahi[mf][3], alo[mf][3]);
        }
        uint32_t bhi[4][2], blo[4][2];
        #pragma unroll
        for (int nf = 0; nf < 4; nf++) {
            const float* wp = &Ws[(k0 + tig) * SW + wn * 32 + nf * 8 + gid];
            split_tf32(wp[0],      bhi[nf][0], blo[nf][0]);
            split_tf32(wp[4 * SW], bhi[nf][1], blo[nf][1]);
        }
        #pragma unroll
        for (int mf = 0; mf < 4; mf++)
            #pragma unroll
            for (int nf = 0; nf < 4; nf++) {
                mma_tf32(acc[mf][nf], ahi[mf], bhi[nf]);
                mma_tf32(acc[mf][nf], ahi[mf], blo[nf]);
                mma_tf32(acc[mf][nf], alo[mf], bhi[nf]);
            }
    }

    // bias + relu, write H back into FH (all F reads complete after barrier)
    float bias0[4], bias1[4];
    #pragma unroll
    for (int nf = 0; nf < 4; nf++) {
        int c = wn * 32 + nf * 8 + 2 * tig;
        bias0[nf] = __ldg(&bW[c]);
        bias1[nf] = __ldg(&bW[c + 1]);
    }
    __syncthreads();

    #pragma unroll
    for (int mf = 0; mf < 4; mf++) {
        int r0 = wm * 64 + mf * 16 + gid;
        #pragma unroll
        for (int nf = 0; nf < 4; nf++) {
            int c = wn * 32 + nf * 8 + 2 * tig;
            float2 v0, v1;
            v0.x = fmaxf(acc[mf][nf][0] + bias0[nf], 0.f);
            v0.y = fmaxf(acc[mf][nf][1] + bias1[nf], 0.f);
            v1.x = fmaxf(acc[mf][nf][2] + bias0[nf], 0.f);
            v1.y = fmaxf(acc[mf][nf][3] + bias1[nf], 0.f);
            *reinterpret_cast<float2*>(&FH[r0 * SF + c])       = v0;
            *reinterpret_cast<float2*>(&FH[(r0 + 8) * SF + c]) = v1;
        }
    }
    __syncthreads();

    // ================= Phase 2: A = H @ Wa (+ b_att1 path 0) =================
    float acc2[4][2][4];
    #pragma unroll
    for (int mf = 0; mf < 4; mf++)
        #pragma unroll
        for (int nf = 0; nf < 2; nf++)
            #pragma unroll
            for (int r = 0; r < 4; r++) acc2[mf][nf][r] = 0.f;

    for (int kb = 0; kb < H1 / 8; kb++) {
        const int k0 = kb * 8;
        uint32_t ahi[4][4], alo[4][4];
        #pragma unroll
        for (int mf = 0; mf < 4; mf++) {
            const float* fp = &FH[(wm * 64 + mf * 16 + gid) * SF + k0 + tig];
            split_tf32(fp[0],          ahi[mf][0], alo[mf][0]);
            split_tf32(fp[8 * SF],     ahi[mf][1], alo[mf][1]);
            split_tf32(fp[4],          ahi[mf][2], alo[mf][2]);
            split_tf32(fp[8 * SF + 4], ahi[mf][3], alo[mf][3]);
        }
        uint32_t bhi[2][2], blo[2][2];
        #pragma unroll
        for (int nf = 0; nf < 2; nf++) {
            const float* wp = &Wa[(k0 + tig) * SA + wn * 16 + nf * 8 + gid];
            split_tf32(wp[0],      bhi[nf][0], blo[nf][0]);
            split_tf32(wp[4 * SA], bhi[nf][1], blo[nf][1]);
        }
        #pragma unroll
        for (int mf = 0; mf < 4; mf++)
            #pragma unroll
            for (int nf = 0; nf < 2; nf++) {
                mma_tf32(acc2[mf][nf], ahi[mf], bhi[nf]);
                mma_tf32(acc2[mf][nf], ahi[mf], blo[nf]);
                mma_tf32(acc2[mf][nf], alo[mf], bhi[nf]);
            }
    }

    float ba0[2] = {0.f, 0.f}, ba1[2] = {0.f, 0.f};
    if (path == 0) {
        #pragma unroll
        for (int nf = 0; nf < 2; nf++) {
            int c = wn * 16 + nf * 8 + 2 * tig;
            ba0[nf] = __ldg(&b_att1[c]);
            ba1[nf] = __ldg(&b_att1[c + 1]);
        }
    }

    #pragma unroll
    for (int mf = 0; mf < 4; mf++) {
        int r0 = wm * 64 + mf * 16 + gid;
        #pragma unroll
        for (int nf = 0; nf < 2; nf++) {
            int c = wn * 16 + nf * 8 + 2 * tig;
            if (r0 < valid) {
                float2 v;
                v.x = acc2[mf][nf][0] + ba0[nf];
                v.y = acc2[mf][nf][1] + ba1[nf];
                *reinterpret_cast<float2*>(&Aout[(size_t)(node0 + r0) * H2 + c]) = v;
            }
            if (r0 + 8 < valid) {
                float2 v;
                v.x = acc2[mf][nf][2] + ba0[nf];
                v.y = acc2[mf][nf][3] + ba1[nf];
                *reinterpret_cast<float2*>(&Aout[(size_t)(node0 + r0 + 8) * H2 + c]) = v;
            }
        }
    }
}

// ---------------- Edge kernel ----------------
// 4 edges per warp, 8 lanes per edge, float4 gathers.
// out[e] = relu(A1[n1] + A2[n2]) . W_att2 + b_att2
extern "C" __global__ void __launch_bounds__(256)
edge_kernel(const void* __restrict__ edges_raw,
            const float* __restrict__ W_att2,
            const float* __restrict__ b_att2,
            float* __restrict__ out,
            int nEdges)
{
    const int warp = (blockIdx.x * blockDim.x + threadIdx.x) >> 5;
    const int lane = threadIdx.x & 31;
    const int sub  = lane >> 3;        // edge slot within warp (0..3)
    const int c    = lane & 7;         // 8-float chunk within edge (0..7)

    const long long e = (long long)warp * 4 + sub;
    if (e >= nEdges) return;           // group-uniform exit (all 8 lanes share e)

    int n1, n2;
    if (g_edges_are_i64) {
        const longlong2 ed =
            *reinterpret_cast<const longlong2*>((const char*)edges_raw + 16 * e);
        n1 = (int)ed.x;
        n2 = (int)ed.y;
    } else {
        const int2 ed =
            *reinterpret_cast<const int2*>((const char*)edges_raw + 8 * e);
        n1 = ed.x;
        n2 = ed.y;
    }

    const float4* pa = reinterpret_cast<const float4*>(&g_A1[(size_t)n1 * H2 + c * 8]);
    const float4* pb = reinterpret_cast<const float4*>(&g_A2[(size_t)n2 * H2 + c * 8]);
    const float4 a0 = pa[0], a1 = pa[1];
    const float4 b0 = pb[0], b1 = pb[1];
    const float4 w0 = __ldg(reinterpret_cast<const float4*>(&W_att2[c * 8]));
    const float4 w1 = __ldg(reinterpret_cast<const float4*>(&W_att2[c * 8 + 4]));

    float s;
    s  = fmaxf(a0.x + b0.x, 0.f) * w0.x;
    s  = fmaf(fmaxf(a0.y + b0.y, 0.f), w0.y, s);
    s  = fmaf(fmaxf(a0.z + b0.z, 0.f), w0.z, s);
    s  = fmaf(fmaxf(a0.w + b0.w, 0.f), w0.w, s);
    s  = fmaf(fmaxf(a1.x + b1.x, 0.f), w1.x, s);
    s  = fmaf(fmaxf(a1.y + b1.y, 0.f), w1.y, s);
    s  = fmaf(fmaxf(a1.z + b1.z, 0.f), w1.z, s);
    s  = fmaf(fmaxf(a1.w + b1.w, 0.f), w1.w, s);

    // reduce within the 8-lane group
    const unsigned gmask = 0xFFu << (sub * 8);
    s += __shfl_xor_sync(gmask, s, 1);
    s += __shfl_xor_sync(gmask, s, 2);
    s += __shfl_xor_sync(gmask, s, 4);

    if (c == 0) out[e] = s + __ldg(&b_att2[0]);
}

// ---------------- Launch ----------------
extern "C" void kernel_launch(void* const* d_in, const int* in_sizes, int n_in,
                              void* d_out, int out_size)
{
    const float* features = (const float*)d_in[0];
    const void*  edges    = d_in[1];
    const float* W_nb     = (const float*)d_in[2];
    const float* b_nb     = (const float*)d_in[3];
    const float* W_self   = (const float*)d_in[4];
    const float* b_self   = (const float*)d_in[5];
    const float* W_att1   = (const float*)d_in[6];
    const float* b_att1   = (const float*)d_in[7];
    const float* W_att2   = (const float*)d_in[8];
    const float* b_att2   = (const float*)d_in[9];
    float* out = (float*)d_out;

    const int nNodes = in_sizes[0] / D_FEAT;
    const int nEdges = in_sizes[1] / 2;

    cudaFuncSetAttribute(node_precompute_kernel,
                         cudaFuncAttributeMaxDynamicSharedMemorySize, NODE_SMEM_BYTES);

    dim3 gridN((nNodes + TM - 1) / TM, 2);
    node_precompute_kernel<<<gridN, 256, NODE_SMEM_BYTES>>>(
        features, (const int*)edges, W_nb, b_nb, W_self, b_self, W_att1, b_att1, nNodes);

    const int edgesPerBlock = (256 / 32) * 4;   // 8 warps x 4 edges
    int gridE = (nEdges + edgesPerBlock - 1) / edgesPerBlock;
    edge_kernel<<<gridE, 256>>>(edges, W_att2, b_att2, out, nEdges);
}